// round 5
// baseline (speedup 1.0000x reference)
#include <cuda_runtime.h>
#include <cuda_bf16.h>
#include <cstdint>

// Block-sparse linear on tensor cores (mma.sync bf16, plain sm_100 target):
//   out[M,N] = data[M,K] @ (weight[N,K], inactive 32x32 blocks skipped)^T + bias
//   fp32 x ~ hi(bf16) + lo(bf16);  D += Ah*Bh + Ah*Bl + Al*Bh  (fp32 accum)
//
// Stage 1: block_mask_kernel  : 32x32 mask tile -> active bit
// Stage 2: compact4_kernel    : per group of 4 nb rows, union kb list + 4-bit mask
// Stage 3: convert_split      : fp32 -> (hi,lo) bf16 for data and weight
// Stage 4: bs_mma_kernel      : CTA 128(M) x 128(N), 8 warps (2x4), warp-exact
//                               block skipping, cp.async double buffer, HMMA.

#define MMAX 4096
#define NMAX 4096
#define KMAX 4096
#define NBMAX 128
#define KBMAX 128
#define NGMAX 32

__device__ int g_bm[NBMAX * KBMAX];
__device__ int g_ulist[NGMAX * KBMAX];   // kb | (active4 << 8)
__device__ int g_ucnt[NGMAX];
__device__ __nv_bfloat16 g_dhi[(size_t)MMAX * KMAX];
__device__ __nv_bfloat16 g_dlo[(size_t)MMAX * KMAX];
__device__ __nv_bfloat16 g_whi[(size_t)NMAX * KMAX];
__device__ __nv_bfloat16 g_wlo[(size_t)NMAX * KMAX];

// ---------------------------------------------------------------------------
// helpers
// ---------------------------------------------------------------------------
__device__ __forceinline__ uint32_t smem_u32(const void* p) {
    return (uint32_t)__cvta_generic_to_shared(p);
}

#define CP_ASYNC16(dst, src) \
    asm volatile("cp.async.cg.shared.global [%0], [%1], 16;" \
                 :: "r"(dst), "l"(src) : "memory")
#define CP_COMMIT() asm volatile("cp.async.commit_group;" ::: "memory")
#define CP_WAIT(n)  asm volatile("cp.async.wait_group %0;" :: "n"(n) : "memory")

__device__ __forceinline__ void ldsm4(uint32_t (&r)[4], uint32_t addr) {
    asm volatile("ldmatrix.sync.aligned.m8n8.x4.shared.b16 {%0,%1,%2,%3}, [%4];"
                 : "=r"(r[0]), "=r"(r[1]), "=r"(r[2]), "=r"(r[3]) : "r"(addr));
}

__device__ __forceinline__ void mma16816(float (&d)[4], const uint32_t (&a)[4],
                                         uint32_t b0, uint32_t b1) {
    asm volatile(
        "mma.sync.aligned.m16n8k16.row.col.f32.bf16.bf16.f32 "
        "{%0,%1,%2,%3}, {%4,%5,%6,%7}, {%8,%9}, {%0,%1,%2,%3};"
        : "+f"(d[0]), "+f"(d[1]), "+f"(d[2]), "+f"(d[3])
        : "r"(a[0]), "r"(a[1]), "r"(a[2]), "r"(a[3]), "r"(b0), "r"(b1));
}

// smem tile: rows of 32 bf16 (64B data) padded to 80B pitch.
// ldmatrix 8-row groups: line index (5*r + koff/16) mod 8 -> conflict-free.
__device__ __forceinline__ uint32_t frag_addr(uint32_t base, int row0, int ks,
                                              int lane) {
    const int r = row0 + ((lane >> 3) & 1) * 8 + (lane & 7);
    const int koff = ks * 32 + (lane >> 4) * 16;
    return base + r * 80 + koff;
}

// ---------------------------------------------------------------------------
// Stage 1: block activity
// ---------------------------------------------------------------------------
__global__ void block_mask_kernel(const int* __restrict__ mask, int K, int Kb) {
    const int kb = blockIdx.x, nb = blockIdx.y, lane = threadIdx.x;
    const int4* row = reinterpret_cast<const int4*>(
        mask + (size_t)(nb * 32 + lane) * (size_t)K + (size_t)kb * 32);
    int acc = 0;
#pragma unroll
    for (int c = 0; c < 8; ++c) { int4 v = row[c]; acc |= v.x | v.y | v.z | v.w; }
    unsigned any = __ballot_sync(0xFFFFFFFFu, acc != 0);
    if (lane == 0) g_bm[nb * Kb + kb] = (any != 0u) ? 1 : 0;
}

// ---------------------------------------------------------------------------
// Stage 2: union list per group of 4 nb rows
// ---------------------------------------------------------------------------
__global__ void compact4_kernel(int Ng, int Kb) {
    const int ng = blockIdx.x * blockDim.x + threadIdx.x;
    if (ng >= Ng) return;
    int cnt = 0;
    for (int kb = 0; kb < Kb; ++kb) {
        int m4 = 0;
#pragma unroll
        for (int j = 0; j < 4; ++j)
            if (g_bm[(ng * 4 + j) * Kb + kb]) m4 |= 1 << j;
        if (m4) { g_ulist[ng * Kb + cnt] = kb | (m4 << 8); ++cnt; }
    }
    g_ucnt[ng] = cnt;
}

// ---------------------------------------------------------------------------
// Stage 3: fp32 -> (hi, lo) bf16 split.  which: 0=data, 1=weight
// ---------------------------------------------------------------------------
__device__ __forceinline__ void split1(float x, unsigned short& h, unsigned short& l) {
    __nv_bfloat16 bh = __float2bfloat16_rn(x);
    float r = x - __bfloat162float(bh);
    __nv_bfloat16 bl = __float2bfloat16_rn(r);
    h = *reinterpret_cast<unsigned short*>(&bh);
    l = *reinterpret_cast<unsigned short*>(&bl);
}

__global__ void convert_split_kernel(const float* __restrict__ src, int which, int n4) {
    const int i = blockIdx.x * blockDim.x + threadIdx.x;
    if (i >= n4) return;
    __nv_bfloat16* hi = which ? g_whi : g_dhi;
    __nv_bfloat16* lo = which ? g_wlo : g_dlo;
    float4 v = reinterpret_cast<const float4*>(src)[i];
    ushort4 h, l;
    split1(v.x, h.x, l.x); split1(v.y, h.y, l.y);
    split1(v.z, h.z, l.z); split1(v.w, h.w, l.w);
    reinterpret_cast<ushort4*>(hi)[i] = h;
    reinterpret_cast<ushort4*>(lo)[i] = l;
}

// ---------------------------------------------------------------------------
// Stage 4: HMMA GEMM.
// smem buffer (x2): A_hi[128x80] | A_lo | B_hi[128x80] | B_lo  = 40960 B
// ---------------------------------------------------------------------------
#define RA_HI 0
#define RA_LO 10240
#define RB_HI 20480
#define RB_LO 30720
#define BUFSZ 40960

__global__ void __launch_bounds__(256, 1) bs_mma_kernel(
    const float* __restrict__ bias, float* __restrict__ out,
    int M, int N, int K, int Kb)
{
    extern __shared__ char smem[];
    const uint32_t sb = smem_u32(smem);
    const int tid = threadIdx.x;
    const int lane = tid & 31, wid = tid >> 5;
    const int wm = wid >> 2;   // 0..1 : M half (64 rows)
    const int wn = wid & 3;    // 0..3 : nb block-row within group
    const int ng = blockIdx.x;
    const int m0 = blockIdx.y * 128;
    const int nb0 = ng * 4;

    const int ucnt = g_ucnt[ng];
    const int* __restrict__ ulist = g_ulist + ng * Kb;

    float acc[4][4][4];
#pragma unroll
    for (int i = 0; i < 4; ++i)
#pragma unroll
        for (int j = 0; j < 4; ++j)
#pragma unroll
            for (int c = 0; c < 4; ++c) acc[i][j][c] = 0.0f;

    // ---- cp.async issue for iteration 'it'
    auto issue = [&](int it) {
        const int entry = ulist[it];
        const int kb = entry & 0xFF;
        const int m4 = (entry >> 8) & 0xF;
        const uint32_t buf = sb + (it & 1) * BUFSZ;
#pragma unroll
        for (int t = 0; t < 2; ++t) {
            const int idx = tid + 256 * t;      // 512 chunks of 16B
            const int r = idx >> 2;             // row 0..127
            const int c = idx & 3;              // 16B chunk in 64B row
            const uint32_t soff = r * 80 + c * 16;
            const size_t aoff = (size_t)(m0 + r) * (size_t)K + kb * 32 + c * 8;
            CP_ASYNC16(buf + RA_HI + soff, g_dhi + aoff);
            CP_ASYNC16(buf + RA_LO + soff, g_dlo + aoff);
            if ((m4 >> (r >> 5)) & 1) {
                const size_t woff =
                    (size_t)(nb0 * 32 + r) * (size_t)K + kb * 32 + c * 8;
                CP_ASYNC16(buf + RB_HI + soff, g_whi + woff);
                CP_ASYNC16(buf + RB_LO + soff, g_wlo + woff);
            }
        }
        CP_COMMIT();
    };

    if (ucnt > 0) issue(0);

    for (int it = 0; it < ucnt; ++it) {
        if (it + 1 < ucnt) { issue(it + 1); CP_WAIT(1); }
        else               { CP_WAIT(0); }
        __syncthreads();

        const int m4 = (ulist[it] >> 8) & 0xF;
        const uint32_t buf = sb + (it & 1) * BUFSZ;

        if ((m4 >> wn) & 1) {
#pragma unroll
            for (int ks = 0; ks < 2; ++ks) {
                uint32_t aH[4][4], aL[4][4], bH[2][4], bL[2][4];
#pragma unroll
                for (int i = 0; i < 4; ++i) {
                    ldsm4(aH[i], frag_addr(buf + RA_HI, wm * 64 + i * 16, ks, lane));
                    ldsm4(aL[i], frag_addr(buf + RA_LO, wm * 64 + i * 16, ks, lane));
                }
#pragma unroll
                for (int p = 0; p < 2; ++p) {
                    ldsm4(bH[p], frag_addr(buf + RB_HI, wn * 32 + p * 16, ks, lane));
                    ldsm4(bL[p], frag_addr(buf + RB_LO, wn * 32 + p * 16, ks, lane));
                }
#pragma unroll
                for (int i = 0; i < 4; ++i)
#pragma unroll
                    for (int jn = 0; jn < 4; ++jn) {
                        const int p = jn >> 1, h = jn & 1;
                        mma16816(acc[i][jn], aH[i], bH[p][h], bH[p][h + 2]);
                        mma16816(acc[i][jn], aH[i], bL[p][h], bL[p][h + 2]);
                        mma16816(acc[i][jn], aL[i], bH[p][h], bH[p][h + 2]);
                    }
            }
        }
        __syncthreads();
    }

    // ---- epilogue: acc + bias -> out (inactive rows: acc==0 -> bias only)
    const int row_l = lane >> 2;
    const int col_l = (lane & 3) * 2;
#pragma unroll
    for (int i = 0; i < 4; ++i) {
        const int rg = m0 + wm * 64 + i * 16 + row_l;
#pragma unroll
        for (int jn = 0; jn < 4; ++jn) {
            const int cg = ng * 128 + wn * 32 + jn * 8 + col_l;
            const float b0 = bias[cg], b1 = bias[cg + 1];
            float2 v0 = make_float2(acc[i][jn][0] + b0, acc[i][jn][1] + b1);
            float2 v1 = make_float2(acc[i][jn][2] + b0, acc[i][jn][3] + b1);
            *reinterpret_cast<float2*>(out + (size_t)rg * (size_t)N + cg) = v0;
            *reinterpret_cast<float2*>(out + (size_t)(rg + 8) * (size_t)N + cg) = v1;
        }
    }
}

// ---------------------------------------------------------------------------
// Launch
// ---------------------------------------------------------------------------
extern "C" void kernel_launch(void* const* d_in, const int* in_sizes, int n_in,
                              void* d_out, int out_size) {
    const float* data   = (const float*)d_in[0];  // [B,S,K] -> [M,K]
    const int*   mask   = (const int*)  d_in[1];  // [N,K]
    const float* weight = (const float*)d_in[2];  // [N,K]
    const float* bias   = (const float*)d_in[3];  // [N]
    float* out = (float*)d_out;                   // [M,N]

    const int N  = in_sizes[3];
    const int K  = in_sizes[2] / N;
    const int M  = in_sizes[0] / K;
    const int Nb = N / 32;
    const int Kb = K / 32;
    const int Ng = Nb / 4;

    block_mask_kernel<<<dim3(Kb, Nb), 32>>>(mask, K, Kb);
    compact4_kernel<<<(Ng + 127) / 128, 128>>>(Ng, Kb);

    const int n4d = (M * K) / 4;
    const int n4w = (N * K) / 4;
    convert_split_kernel<<<(n4d + 255) / 256, 256>>>(data, 0, n4d);
    convert_split_kernel<<<(n4w + 255) / 256, 256>>>(weight, 1, n4w);

    const int smem_bytes = 2 * BUFSZ;  // 81920
    cudaFuncSetAttribute(bs_mma_kernel,
                         cudaFuncAttributeMaxDynamicSharedMemorySize, smem_bytes);
    bs_mma_kernel<<<dim3(Ng, M / 128), 256, smem_bytes>>>(bias, out, M, N, K, Kb);
}